// round 10
// baseline (speedup 1.0000x reference)
#include <cuda_runtime.h>

#define BB       4096
#define VOCABN   50000
#define FF       64
#define K_PAD    50688       // 9 * 5632 = 198 * 256, B zero-padded beyond 50000
#define K_SPLITS 9
#define K_PER    5632        // 44 * 128
#define ITERS    44
#define TILE_K   128
#define M_TILES  32
#define NB       64          // V cols only; c handled via dp4a
#define BROW8    144         // int8 smem row stride (128 data + 16 pad)
#define LIMB_B   (NB * BROW8)   // 9216 bytes per limb per stage

// ---- device-global scratch (zero-initialized at load; invariant restored by fm_fin) ----
__device__ __align__(16) signed char g_Bh8[NB * K_PAD];
__device__ __align__(16) signed char g_Bl8[NB * K_PAD];
__device__ __align__(16) signed char g_ch8[K_PAD];
__device__ __align__(16) signed char g_cl8[K_PAD];
__device__ float g_xv[BB * FF];
__device__ float g_xc[BB];
__device__ int   g_maxb[65];

__device__ __forceinline__ unsigned s2u(const void* p) {
    return (unsigned)__cvta_generic_to_shared(p);
}
__device__ __forceinline__ void cp16(void* dst, const void* src) {
    asm volatile("cp.async.cg.shared.global [%0], [%1], 16;"
                 :: "r"(s2u(dst)), "l"(src));
}
__device__ __forceinline__ void ldsm4(unsigned* r, unsigned addr) {
    asm volatile("ldmatrix.sync.aligned.m8n8.x4.shared.b16 {%0,%1,%2,%3}, [%4];"
                 : "=r"(r[0]), "=r"(r[1]), "=r"(r[2]), "=r"(r[3]) : "r"(addr));
}
__device__ __forceinline__ void mma_s8(int* d, const unsigned* a, unsigned b0, unsigned b1) {
    asm volatile(
        "mma.sync.aligned.m16n8k32.row.col.s32.s8.s8.s32 "
        "{%0,%1,%2,%3}, {%4,%5,%6,%7}, {%8,%9}, {%0,%1,%2,%3};"
        : "+r"(d[0]), "+r"(d[1]), "+r"(d[2]), "+r"(d[3])
        : "r"(a[0]), "r"(a[1]), "r"(a[2]), "r"(a[3]), "r"(b0), "r"(b1));
}

// ---------------- pass 1: per-column max |V|, max |c| (4 rows/thread) ----------------
__global__ void fm_scale1(const float* __restrict__ V, const float* __restrict__ bias) {
    __shared__ int smax[65];
    int tid = threadIdx.x, lane = tid & 31;
    if (tid < 65) smax[tid] = 0;
    __syncthreads();

    float4 m4[16];
    #pragma unroll
    for (int j = 0; j < 16; j++) m4[j] = make_float4(0.f, 0.f, 0.f, 0.f);
    float cabs = 0.f;

    #pragma unroll
    for (int q = 0; q < 4; q++) {
        int r = blockIdx.x * 1024 + q * 256 + tid;
        if (r < VOCABN) {
            const float4* vr = (const float4*)(V + (size_t)r * 64);
            float ss = 0.f;
            #pragma unroll
            for (int j = 0; j < 16; j++) {
                float4 v = vr[j];
                ss += v.x*v.x + v.y*v.y + v.z*v.z + v.w*v.w;
                m4[j].x = fmaxf(m4[j].x, fabsf(v.x));
                m4[j].y = fmaxf(m4[j].y, fabsf(v.y));
                m4[j].z = fmaxf(m4[j].z, fabsf(v.z));
                m4[j].w = fmaxf(m4[j].w, fabsf(v.w));
            }
            cabs = fmaxf(cabs, fabsf(bias[r] - 0.5f * ss));
        }
    }
    #pragma unroll
    for (int j = 0; j < 16; j++) {
        float vx = m4[j].x, vy = m4[j].y, vz = m4[j].z, vw = m4[j].w;
        #pragma unroll
        for (int off = 16; off > 0; off >>= 1) {
            vx = fmaxf(vx, __shfl_xor_sync(0xFFFFFFFFu, vx, off));
            vy = fmaxf(vy, __shfl_xor_sync(0xFFFFFFFFu, vy, off));
            vz = fmaxf(vz, __shfl_xor_sync(0xFFFFFFFFu, vz, off));
            vw = fmaxf(vw, __shfl_xor_sync(0xFFFFFFFFu, vw, off));
        }
        if (lane == 0) {
            atomicMax(&smax[j*4+0], __float_as_int(vx));
            atomicMax(&smax[j*4+1], __float_as_int(vy));
            atomicMax(&smax[j*4+2], __float_as_int(vz));
            atomicMax(&smax[j*4+3], __float_as_int(vw));
        }
    }
    #pragma unroll
    for (int off = 16; off > 0; off >>= 1)
        cabs = fmaxf(cabs, __shfl_xor_sync(0xFFFFFFFFu, cabs, off));
    if (lane == 0) atomicMax(&smax[64], __float_as_int(cabs));
    __syncthreads();
    if (tid < 65) atomicMax(&g_maxb[tid], smax[tid]);
}

__device__ __forceinline__ void quant2(float v, float s, signed char& h8, signed char& l8) {
    float q = v * s;
    float h = rintf(q);
    float l = rintf((q - h) * 256.f);
    if (l > 127.f) l = 127.f;
    h8 = (signed char)(int)h;
    l8 = (signed char)(int)l;
}

// ---------------- pass 2: quantize V cols + c into s8 limbs, K-major (4 chunks/block) ----------------
__global__ void fm_prep(const float* __restrict__ V, const float* __restrict__ bias) {
    __shared__ float sm[64][65];
    __shared__ float cs[64];
    __shared__ float ssc[65];
    int tid = threadIdx.x;

    if (tid < 65) {
        float m = __int_as_float(g_maxb[tid]);
        ssc[tid] = (m > 0.f) ? 127.f / m : 1.f;
    }
    __syncthreads();

    for (int chunk = 0; chunk < 4; chunk++) {
        int i0 = blockIdx.x * 256 + chunk * 64;
        for (int idx = tid; idx < 64 * 64; idx += 256) {
            int i = idx >> 6, f = idx & 63;
            int gi = i0 + i;
            sm[i][f] = (gi < VOCABN) ? V[(size_t)gi * 64 + f] : 0.f;
        }
        __syncthreads();
        if (tid < 64) {
            float ssum = 0.f;
            #pragma unroll
            for (int f = 0; f < 64; f++) { float v = sm[tid][f]; ssum += v * v; }
            int gi = i0 + tid;
            cs[tid] = (gi < VOCABN) ? (bias[gi] - 0.5f * ssum) : 0.f;
        }
        __syncthreads();
        for (int idx = tid; idx < 64 * 16; idx += 256) {
            int f = idx >> 4, i4 = (idx & 15) * 4;
            float s = ssc[f];
            char4 h4, l4;
            quant2(sm[i4 + 0][f], s, (signed char&)h4.x, (signed char&)l4.x);
            quant2(sm[i4 + 1][f], s, (signed char&)h4.y, (signed char&)l4.y);
            quant2(sm[i4 + 2][f], s, (signed char&)h4.z, (signed char&)l4.z);
            quant2(sm[i4 + 3][f], s, (signed char&)h4.w, (signed char&)l4.w);
            *(char4*)&g_Bh8[(size_t)f * K_PAD + i0 + i4] = h4;
            *(char4*)&g_Bl8[(size_t)f * K_PAD + i0 + i4] = l4;
        }
        if (tid < 64) {
            signed char h8, l8;
            quant2(cs[tid], ssc[64], h8, l8);
            g_ch8[i0 + tid] = h8;
            g_cl8[i0 + tid] = l8;
        }
        __syncthreads();   // sm/cs reused next chunk
    }
}

// dequant scale: inv = 1/(256*s), s = (max>0 ? 127/max : 1)
__device__ __forceinline__ double getinv(int n) {
    float m = __int_as_float(g_maxb[n]);
    return (m > 0.f) ? (double)m / 32512.0 : (1.0 / 256.0);
}

// ---------------- main: split-K s8 GEMM (exact s32) + dp4a linear term ----------------
__global__ void __launch_bounds__(128, 2) fm_main(const int* __restrict__ x) {
    __shared__ __align__(16) signed char sB[2][2][NB][BROW8];   // 36.9KB
    __shared__ __align__(16) signed char sC[2][2][128];          // 512B

    const int tid  = threadIdx.x;
    const int w    = tid >> 5;
    const int lane = tid & 31;
    const int gid  = lane >> 2;
    const int t4   = (lane & 3) * 4;
    const int t2   = (lane & 3) * 2;
    const int mt   = blockIdx.x & (M_TILES - 1);
    const int ks   = blockIdx.x >> 5;
    const int m0   = mt * 128;
    const int k0   = ks * K_PER;

    const int* xr[4];
    bool nl[4];
    #pragma unroll
    for (int j = 0; j < 4; j++) {
        int r = m0 + w * 32 + j * 8 + gid;
        xr[j] = x + (size_t)r * VOCABN;
        nl[j] = (r != BB - 1);
    }

    int accH[8][2][4], accL[8][2][4];
    #pragma unroll
    for (int n = 0; n < 8; n++)
        #pragma unroll
        for (int m = 0; m < 2; m++)
            #pragma unroll
            for (int i = 0; i < 4; i++) { accH[n][m][i] = 0; accL[n][m][i] = 0; }
    int cH[4] = {0, 0, 0, 0}, cL[4] = {0, 0, 0, 0};

    // stage k128: B = 2*64*8 = 1024 chunks (8/thread); c = 16 chunks
    auto stageB = [&](int st, int k) {
        #pragma unroll
        for (int j = 0; j < 8; j++) {
            int c = tid + j * 128;
            int limb = (c >= 512) ? 1 : 0;
            int cc = c - limb * 512;
            int n = cc >> 3, ch = cc & 7;
            const signed char* g = limb ? g_Bl8 : g_Bh8;
            cp16(&sB[st][limb][n][ch * 16], g + (size_t)n * K_PAD + k + ch * 16);
        }
        if (tid < 16) {
            int limb = tid >> 3, ch = tid & 7;
            const signed char* g = limb ? g_cl8 : g_ch8;
            cp16(&sC[st][limb][ch * 16], g + k + ch * 16);
        }
        asm volatile("cp.async.commit_group;");
    };

    // depth-2 A prefetch: raw[pb] loaded at step g, consumed at step g+2
    int4 raw[2][8];
    unsigned pa[8];
    auto loadA = [&](int pb, int cb) {
        #pragma unroll
        for (int mf = 0; mf < 2; mf++)
            #pragma unroll
            for (int q = 0; q < 4; q++) {
                const int* p = xr[mf * 2 + (q & 1)];
                int c = cb + (q >> 1) * 16 + t4;
                bool ok = nl[mf * 2 + (q & 1)] | (c < VOCABN);
                raw[pb][mf * 4 + q] = ok ? *(const int4*)(p + c) : make_int4(0, 0, 0, 0);
            }
    };
    auto packA = [&](int pb) {
        #pragma unroll
        for (int i = 0; i < 8; i++) {
            int4 v = raw[pb][i];
            pa[i] = (unsigned)v.x | ((unsigned)v.y << 8)
                  | ((unsigned)v.z << 16) | ((unsigned)v.w << 24);
        }
    };

    const unsigned offX4 = (unsigned)((lane & 15) * BROW8 + (lane >> 4) * 16);
    const unsigned sb0 = s2u(&sB[0][0][0][0]);

    auto doLimb = [&](unsigned lb, int (&acc)[8][2][4]) {
        #pragma unroll
        for (int j = 0; j < 4; j++) {
            unsigned bm[4];
            ldsm4(bm, lb + (unsigned)j * (16 * BROW8) + offX4);
            #pragma unroll
            for (int mf = 0; mf < 2; mf++) {
                mma_s8(acc[2 * j][mf],     pa + mf * 4, bm[0], bm[2]);
                mma_s8(acc[2 * j + 1][mf], pa + mf * 4, bm[1], bm[3]);
            }
        }
    };

    stageB(0, k0);
    loadA(0, k0);           // g = 0
    loadA(1, k0 + 32);      // g = 1

    for (int it = 0; it < ITERS; it++) {
        const int p = it & 1;
        __syncthreads();
        if (it + 1 < ITERS) {
            stageB(p ^ 1, k0 + (it + 1) * TILE_K);
            asm volatile("cp.async.wait_group 1;");
        } else {
            asm volatile("cp.async.wait_group 0;");
        }
        __syncthreads();

        const unsigned stb = sb0 + (unsigned)p * (2 * LIMB_B);
        #pragma unroll
        for (int s = 0; s < 4; s++) {
            const int g = it * 4 + s;
            const int pb = g & 1;
            packA(pb);                          // consume batch loaded at g-2
            loadA(pb, k0 + (g + 2) * 32);       // issue batch for g+2
            // linear (c) term via dp4a on ALU pipe
            {
                int w0h = *(const int*)&sC[p][0][s * 32 + t4];
                int w1h = *(const int*)&sC[p][0][s * 32 + 16 + t4];
                int w0l = *(const int*)&sC[p][1][s * 32 + t4];
                int w1l = *(const int*)&sC[p][1][s * 32 + 16 + t4];
                cH[0] = __dp4a((int)pa[0], w0h, cH[0]);
                cH[1] = __dp4a((int)pa[1], w0h, cH[1]);
                cH[0] = __dp4a((int)pa[2], w1h, cH[0]);
                cH[1] = __dp4a((int)pa[3], w1h, cH[1]);
                cH[2] = __dp4a((int)pa[4], w0h, cH[2]);
                cH[3] = __dp4a((int)pa[5], w0h, cH[3]);
                cH[2] = __dp4a((int)pa[6], w1h, cH[2]);
                cH[3] = __dp4a((int)pa[7], w1h, cH[3]);
                cL[0] = __dp4a((int)pa[0], w0l, cL[0]);
                cL[1] = __dp4a((int)pa[1], w0l, cL[1]);
                cL[0] = __dp4a((int)pa[2], w1l, cL[0]);
                cL[1] = __dp4a((int)pa[3], w1l, cL[1]);
                cL[2] = __dp4a((int)pa[4], w0l, cL[2]);
                cL[3] = __dp4a((int)pa[5], w0l, cL[3]);
                cL[2] = __dp4a((int)pa[6], w1l, cL[2]);
                cL[3] = __dp4a((int)pa[7], w1l, cL[3]);
            }
            doLimb(stb + (unsigned)s * 32, accH);
            doLimb(stb + LIMB_B + (unsigned)s * 32, accL);
        }
    }

    // ---- epilogue: dequant + split-K accumulate ----
    #pragma unroll
    for (int mf = 0; mf < 2; mf++) {
        int rowA = m0 + w * 32 + mf * 16 + gid;
        #pragma unroll
        for (int nf = 0; nf < 8; nf++) {
            #pragma unroll
            for (int cc = 0; cc < 2; cc++) {
                int n = nf * 8 + t2 + cc;
                double inv = getinv(n);
                float v0 = (float)((double)(256LL * accH[nf][mf][cc]     + accL[nf][mf][cc])     * inv);
                float v1 = (float)((double)(256LL * accH[nf][mf][2 + cc] + accL[nf][mf][2 + cc]) * inv);
                atomicAdd(&g_xv[(size_t)rowA * FF + n],       v0);
                atomicAdd(&g_xv[(size_t)(rowA + 8) * FF + n], v1);
            }
        }
    }
    // c term: quad-reduce then one atomic per row slot
    #pragma unroll
    for (int j = 0; j < 4; j++) {
        int h = cH[j], l = cL[j];
        h += __shfl_xor_sync(0xFFFFFFFFu, h, 1);
        h += __shfl_xor_sync(0xFFFFFFFFu, h, 2);
        l += __shfl_xor_sync(0xFFFFFFFFu, l, 1);
        l += __shfl_xor_sync(0xFFFFFFFFu, l, 2);
        if ((lane & 3) == 0) {
            int row = m0 + w * 32 + j * 8 + gid;
            atomicAdd(&g_xc[row],
                      (float)((double)(256LL * h + l) * getinv(64)));
        }
    }
}

// ---------------- finalize: out = g + xc + 0.5||xv||^2; re-zero scratch for next replay ----------------
__global__ void fm_fin(const float* __restrict__ gb, float* __restrict__ out) {
    int t = blockIdx.x * blockDim.x + threadIdx.x;   // 16384 threads
    int b = t >> 2, part = t & 3;
    float4* v = (float4*)&g_xv[(size_t)b * FF + part * 16];
    float ss = 0.f;
    #pragma unroll
    for (int i = 0; i < 4; i++) {
        float4 q = v[i];
        ss += q.x * q.x + q.y * q.y + q.z * q.z + q.w * q.w;
        v[i] = make_float4(0.f, 0.f, 0.f, 0.f);          // restore zero invariant
    }
    ss += __shfl_xor_sync(0xFFFFFFFFu, ss, 1);
    ss += __shfl_xor_sync(0xFFFFFFFFu, ss, 2);
    if (part == 0) {
        out[b] = gb[0] + g_xc[b] + 0.5f * ss;
        g_xc[b] = 0.f;
    }
    if (t < 65) g_maxb[t] = 0;
}

extern "C" void kernel_launch(void* const* d_in, const int* in_sizes, int n_in,
                              void* d_out, int out_size) {
    const int*   x    = (const int*)d_in[0];
    const float* V    = (const float*)d_in[1];
    const float* bias = (const float*)d_in[2];
    const float* gb   = (const float*)d_in[3];
    float* out = (float*)d_out;
    (void)in_sizes; (void)n_in; (void)out_size;

    fm_scale1<<<49, 256>>>(V, bias);
    fm_prep<<<198, 256>>>(V, bias);
    fm_main<<<M_TILES * K_SPLITS, 128>>>(x);
    fm_fin<<<64, 256>>>(gb, out);
}

// round 11
// speedup vs baseline: 1.0518x; 1.0518x over previous
#include <cuda_runtime.h>

#define BB       4096
#define VOCABN   50000
#define FF       64
#define K_PAD    50688       // 9 * 5632 = 792 * 64, B zero-padded beyond 50000
#define K_SPLITS 9
#define K_PER    5632        // 44 * 128
#define ITERS    44
#define TILE_K   128
#define M_TILES  32
#define NB       64          // V cols only; c handled via dp4a
#define BROW8    144         // int8 smem row stride (128 data + 16 pad)
#define LIMB_B   (NB * BROW8)   // 9216 bytes per limb per stage

// ---- device-global scratch (zero-initialized at load; invariant restored by fm_fin) ----
__device__ __align__(16) signed char g_Bh8[NB * K_PAD];
__device__ __align__(16) signed char g_Bl8[NB * K_PAD];
__device__ __align__(16) signed char g_ch8[K_PAD];
__device__ __align__(16) signed char g_cl8[K_PAD];
__device__ float g_xv[BB * FF];
__device__ float g_xc[BB];
__device__ int   g_maxb[65];

__device__ __forceinline__ unsigned s2u(const void* p) {
    return (unsigned)__cvta_generic_to_shared(p);
}
__device__ __forceinline__ void cp16(void* dst, const void* src) {
    asm volatile("cp.async.cg.shared.global [%0], [%1], 16;"
                 :: "r"(s2u(dst)), "l"(src));
}
__device__ __forceinline__ void ldsm4(unsigned* r, unsigned addr) {
    asm volatile("ldmatrix.sync.aligned.m8n8.x4.shared.b16 {%0,%1,%2,%3}, [%4];"
                 : "=r"(r[0]), "=r"(r[1]), "=r"(r[2]), "=r"(r[3]) : "r"(addr));
}
__device__ __forceinline__ void mma_s8(int* d, const unsigned* a, unsigned b0, unsigned b1) {
    asm volatile(
        "mma.sync.aligned.m16n8k32.row.col.s32.s8.s8.s32 "
        "{%0,%1,%2,%3}, {%4,%5,%6,%7}, {%8,%9}, {%0,%1,%2,%3};"
        : "+r"(d[0]), "+r"(d[1]), "+r"(d[2]), "+r"(d[3])
        : "r"(a[0]), "r"(a[1]), "r"(a[2]), "r"(a[3]), "r"(b0), "r"(b1));
}

// ---------------- pass 1: per-column max |V|, max |c| (R9 shape: 1 row/thread) ----------------
__global__ void fm_scale1(const float* __restrict__ V, const float* __restrict__ bias) {
    __shared__ int smax[65];
    int tid = threadIdx.x, lane = tid & 31;
    if (tid < 65) smax[tid] = 0;
    __syncthreads();
    int r = blockIdx.x * 256 + tid;
    float4 m4[16];
    float cabs = 0.f;
    if (r < VOCABN) {
        const float4* vr = (const float4*)(V + (size_t)r * 64);
        float ss = 0.f;
        #pragma unroll
        for (int j = 0; j < 16; j++) {
            float4 v = vr[j];
            ss += v.x*v.x + v.y*v.y + v.z*v.z + v.w*v.w;
            m4[j] = make_float4(fabsf(v.x), fabsf(v.y), fabsf(v.z), fabsf(v.w));
        }
        cabs = fabsf(bias[r] - 0.5f * ss);
    } else {
        #pragma unroll
        for (int j = 0; j < 16; j++) m4[j] = make_float4(0.f, 0.f, 0.f, 0.f);
    }
    #pragma unroll
    for (int j = 0; j < 16; j++) {
        float vx = m4[j].x, vy = m4[j].y, vz = m4[j].z, vw = m4[j].w;
        #pragma unroll
        for (int off = 16; off > 0; off >>= 1) {
            vx = fmaxf(vx, __shfl_xor_sync(0xFFFFFFFFu, vx, off));
            vy = fmaxf(vy, __shfl_xor_sync(0xFFFFFFFFu, vy, off));
            vz = fmaxf(vz, __shfl_xor_sync(0xFFFFFFFFu, vz, off));
            vw = fmaxf(vw, __shfl_xor_sync(0xFFFFFFFFu, vw, off));
        }
        if (lane == 0) {
            atomicMax(&smax[j*4+0], __float_as_int(vx));
            atomicMax(&smax[j*4+1], __float_as_int(vy));
            atomicMax(&smax[j*4+2], __float_as_int(vz));
            atomicMax(&smax[j*4+3], __float_as_int(vw));
        }
    }
    #pragma unroll
    for (int off = 16; off > 0; off >>= 1)
        cabs = fmaxf(cabs, __shfl_xor_sync(0xFFFFFFFFu, cabs, off));
    if (lane == 0) atomicMax(&smax[64], __float_as_int(cabs));
    __syncthreads();
    if (tid < 65) atomicMax(&g_maxb[tid], smax[tid]);
}

__device__ __forceinline__ void quant2(float v, float s, signed char& h8, signed char& l8) {
    float q = v * s;
    float h = rintf(q);
    float l = rintf((q - h) * 256.f);
    if (l > 127.f) l = 127.f;
    h8 = (signed char)(int)h;
    l8 = (signed char)(int)l;
}

// ---------------- pass 2: quantize (R9 shape: 792 blocks, 64 rows each) ----------------
__global__ void fm_prep(const float* __restrict__ V, const float* __restrict__ bias) {
    __shared__ float sm[64][65];
    __shared__ float cs[64];
    __shared__ float ssc[65];
    int i0 = blockIdx.x * 64;
    int tid = threadIdx.x;
    if (tid < 65) {
        float m = __int_as_float(g_maxb[tid]);
        ssc[tid] = (m > 0.f) ? 127.f / m : 1.f;
    }
    for (int idx = tid; idx < 64 * 64; idx += 256) {
        int i = idx >> 6, f = idx & 63;
        int gi = i0 + i;
        sm[i][f] = (gi < VOCABN) ? V[(size_t)gi * 64 + f] : 0.f;
    }
    __syncthreads();
    if (tid < 64) {
        float ssum = 0.f;
        #pragma unroll
        for (int f = 0; f < 64; f++) { float v = sm[tid][f]; ssum += v * v; }
        int gi = i0 + tid;
        cs[tid] = (gi < VOCABN) ? (bias[gi] - 0.5f * ssum) : 0.f;
    }
    __syncthreads();
    for (int idx = tid; idx < 64 * 16; idx += 256) {
        int f = idx >> 4, i4 = (idx & 15) * 4;
        float s = ssc[f];
        char4 h4, l4;
        quant2(sm[i4 + 0][f], s, (signed char&)h4.x, (signed char&)l4.x);
        quant2(sm[i4 + 1][f], s, (signed char&)h4.y, (signed char&)l4.y);
        quant2(sm[i4 + 2][f], s, (signed char&)h4.z, (signed char&)l4.z);
        quant2(sm[i4 + 3][f], s, (signed char&)h4.w, (signed char&)l4.w);
        *(char4*)&g_Bh8[(size_t)f * K_PAD + i0 + i4] = h4;
        *(char4*)&g_Bl8[(size_t)f * K_PAD + i0 + i4] = l4;
    }
    if (tid < 64) {
        signed char h8, l8;
        quant2(cs[tid], ssc[64], h8, l8);
        g_ch8[i0 + tid] = h8;
        g_cl8[i0 + tid] = l8;
    }
}

// dequant scale: inv = 1/(256*s), s = (max>0 ? 127/max : 1)
__device__ __forceinline__ double getinv(int n) {
    float m = __int_as_float(g_maxb[n]);
    return (m > 0.f) ? (double)m / 32512.0 : (1.0 / 256.0);
}

// ---------------- main: split-K s8 GEMM (exact s32) + dp4a linear term ----------------
__global__ void __launch_bounds__(128, 2) fm_main(const int* __restrict__ x) {
    __shared__ __align__(16) signed char sB[2][2][NB][BROW8];   // 36.9KB
    __shared__ __align__(16) signed char sC[2][2][128];          // 512B

    const int tid  = threadIdx.x;
    const int w    = tid >> 5;
    const int lane = tid & 31;
    const int gid  = lane >> 2;
    const int t4   = (lane & 3) * 4;
    const int t2   = (lane & 3) * 2;
    const int mt   = blockIdx.x & (M_TILES - 1);
    const int ks   = blockIdx.x >> 5;
    const int m0   = mt * 128;
    const int k0   = ks * K_PER;

    const int* xr[4];
    bool nl[4];
    #pragma unroll
    for (int j = 0; j < 4; j++) {
        int r = m0 + w * 32 + j * 8 + gid;
        xr[j] = x + (size_t)r * VOCABN;
        nl[j] = (r != BB - 1);
    }

    int accH[8][2][4], accL[8][2][4];
    #pragma unroll
    for (int n = 0; n < 8; n++)
        #pragma unroll
        for (int m = 0; m < 2; m++)
            #pragma unroll
            for (int i = 0; i < 4; i++) { accH[n][m][i] = 0; accL[n][m][i] = 0; }
    int cH[4] = {0, 0, 0, 0}, cL[4] = {0, 0, 0, 0};

    // stage k128: B = 2*64*8 = 1024 chunks (8/thread); c = 16 chunks
    auto stageB = [&](int st, int k) {
        #pragma unroll
        for (int j = 0; j < 8; j++) {
            int c = tid + j * 128;
            int limb = (c >= 512) ? 1 : 0;
            int cc = c - limb * 512;
            int n = cc >> 3, ch = cc & 7;
            const signed char* g = limb ? g_Bl8 : g_Bh8;
            cp16(&sB[st][limb][n][ch * 16], g + (size_t)n * K_PAD + k + ch * 16);
        }
        if (tid < 16) {
            int limb = tid >> 3, ch = tid & 7;
            const signed char* g = limb ? g_cl8 : g_ch8;
            cp16(&sC[st][limb][ch * 16], g + k + ch * 16);
        }
        asm volatile("cp.async.commit_group;");
    };

    // depth-2 A prefetch: raw[pb] loaded at step g, consumed at step g+2
    int4 raw[2][8];
    unsigned pa[8];
    auto loadA = [&](int pb, int cb) {
        #pragma unroll
        for (int mf = 0; mf < 2; mf++)
            #pragma unroll
            for (int q = 0; q < 4; q++) {
                const int* p = xr[mf * 2 + (q & 1)];
                int c = cb + (q >> 1) * 16 + t4;
                bool ok = nl[mf * 2 + (q & 1)] | (c < VOCABN);
                raw[pb][mf * 4 + q] = ok ? *(const int4*)(p + c) : make_int4(0, 0, 0, 0);
            }
    };
    auto packA = [&](int pb) {
        #pragma unroll
        for (int i = 0; i < 8; i++) {
            int4 v = raw[pb][i];
            pa[i] = (unsigned)v.x | ((unsigned)v.y << 8)
                  | ((unsigned)v.z << 16) | ((unsigned)v.w << 24);
        }
    };

    const unsigned offX4 = (unsigned)((lane & 15) * BROW8 + (lane >> 4) * 16);
    const unsigned sb0 = s2u(&sB[0][0][0][0]);

    auto doLimb = [&](unsigned lb, int (&acc)[8][2][4]) {
        #pragma unroll
        for (int j = 0; j < 4; j++) {
            unsigned bm[4];
            ldsm4(bm, lb + (unsigned)j * (16 * BROW8) + offX4);
            #pragma unroll
            for (int mf = 0; mf < 2; mf++) {
                mma_s8(acc[2 * j][mf],     pa + mf * 4, bm[0], bm[2]);
                mma_s8(acc[2 * j + 1][mf], pa + mf * 4, bm[1], bm[3]);
            }
        }
    };

    stageB(0, k0);
    loadA(0, k0);           // g = 0
    loadA(1, k0 + 32);      // g = 1

    for (int it = 0; it < ITERS; it++) {
        const int p = it & 1;
        __syncthreads();
        if (it + 1 < ITERS) {
            stageB(p ^ 1, k0 + (it + 1) * TILE_K);
            asm volatile("cp.async.wait_group 1;");
        } else {
            asm volatile("cp.async.wait_group 0;");
        }
        __syncthreads();

        // hoist the c-term weights for all 4 s-steps into registers up front
        int wc[4][4];
        #pragma unroll
        for (int s = 0; s < 4; s++) {
            wc[s][0] = *(const int*)&sC[p][0][s * 32 + t4];
            wc[s][1] = *(const int*)&sC[p][0][s * 32 + 16 + t4];
            wc[s][2] = *(const int*)&sC[p][1][s * 32 + t4];
            wc[s][3] = *(const int*)&sC[p][1][s * 32 + 16 + t4];
        }

        const unsigned stb = sb0 + (unsigned)p * (2 * LIMB_B);
        #pragma unroll
        for (int s = 0; s < 4; s++) {
            const int g = it * 4 + s;
            const int pb = g & 1;
            packA(pb);                          // consume batch loaded at g-2
            loadA(pb, k0 + (g + 2) * 32);       // issue batch for g+2
            // linear (c) term via dp4a on ALU pipe
            {
                cH[0] = __dp4a((int)pa[0], wc[s][0], cH[0]);
                cH[1] = __dp4a((int)pa[1], wc[s][0], cH[1]);
                cH[0] = __dp4a((int)pa[2], wc[s][1], cH[0]);
                cH[1] = __dp4a((int)pa[3], wc[s][1], cH[1]);
                cH[2] = __dp4a((int)pa[4], wc[s][0], cH[2]);
                cH[3] = __dp4a((int)pa[5], wc[s][0], cH[3]);
                cH[2] = __dp4a((int)pa[6], wc[s][1], cH[2]);
                cH[3] = __dp4a((int)pa[7], wc[s][1], cH[3]);
                cL[0] = __dp4a((int)pa[0], wc[s][2], cL[0]);
                cL[1] = __dp4a((int)pa[1], wc[s][2], cL[1]);
                cL[0] = __dp4a((int)pa[2], wc[s][3], cL[0]);
                cL[1] = __dp4a((int)pa[3], wc[s][3], cL[1]);
                cL[2] = __dp4a((int)pa[4], wc[s][2], cL[2]);
                cL[3] = __dp4a((int)pa[5], wc[s][2], cL[3]);
                cL[2] = __dp4a((int)pa[6], wc[s][3], cL[2]);
                cL[3] = __dp4a((int)pa[7], wc[s][3], cL[3]);
            }
            doLimb(stb + (unsigned)s * 32, accH);
            doLimb(stb + LIMB_B + (unsigned)s * 32, accL);
        }
    }

    // ---- epilogue: dequant + split-K accumulate ----
    #pragma unroll
    for (int mf = 0; mf < 2; mf++) {
        int rowA = m0 + w * 32 + mf * 16 + gid;
        #pragma unroll
        for (int nf = 0; nf < 8; nf++) {
            #pragma unroll
            for (int cc = 0; cc < 2; cc++) {
                int n = nf * 8 + t2 + cc;
                double inv = getinv(n);
                float v0 = (float)((double)(256LL * accH[nf][mf][cc]     + accL[nf][mf][cc])     * inv);
                float v1 = (float)((double)(256LL * accH[nf][mf][2 + cc] + accL[nf][mf][2 + cc]) * inv);
                atomicAdd(&g_xv[(size_t)rowA * FF + n],       v0);
                atomicAdd(&g_xv[(size_t)(rowA + 8) * FF + n], v1);
            }
        }
    }
    // c term: quad-reduce then one atomic per row slot
    #pragma unroll
    for (int j = 0; j < 4; j++) {
        int h = cH[j], l = cL[j];
        h += __shfl_xor_sync(0xFFFFFFFFu, h, 1);
        h += __shfl_xor_sync(0xFFFFFFFFu, h, 2);
        l += __shfl_xor_sync(0xFFFFFFFFu, l, 1);
        l += __shfl_xor_sync(0xFFFFFFFFu, l, 2);
        if ((lane & 3) == 0) {
            int row = m0 + w * 32 + j * 8 + gid;
            atomicAdd(&g_xc[row],
                      (float)((double)(256LL * h + l) * getinv(64)));
        }
    }
}

// ---------------- finalize: out = g + xc + 0.5||xv||^2; re-zero scratch ----------------
__global__ void fm_fin(const float* __restrict__ gb, float* __restrict__ out) {
    int t = blockIdx.x * blockDim.x + threadIdx.x;   // 16384 threads
    int b = t >> 2, part = t & 3;
    float4* v = (float4*)&g_xv[(size_t)b * FF + part * 16];
    float ss = 0.f;
    #pragma unroll
    for (int i = 0; i < 4; i++) {
        float4 q = v[i];
        ss += q.x * q.x + q.y * q.y + q.z * q.z + q.w * q.w;
        v[i] = make_float4(0.f, 0.f, 0.f, 0.f);          // restore zero invariant
    }
    ss += __shfl_xor_sync(0xFFFFFFFFu, ss, 1);
    ss += __shfl_xor_sync(0xFFFFFFFFu, ss, 2);
    if (part == 0) {
        out[b] = gb[0] + g_xc[b] + 0.5f * ss;
        g_xc[b] = 0.f;
    }
    if (t < 65) g_maxb[t] = 0;
}

extern "C" void kernel_launch(void* const* d_in, const int* in_sizes, int n_in,
                              void* d_out, int out_size) {
    const int*   x    = (const int*)d_in[0];
    const float* V    = (const float*)d_in[1];
    const float* bias = (const float*)d_in[2];
    const float* gb   = (const float*)d_in[3];
    float* out = (float*)d_out;
    (void)in_sizes; (void)n_in; (void)out_size;

    fm_scale1<<<196, 256>>>(V, bias);
    fm_prep<<<K_PAD / 64, 256>>>(V, bias);
    fm_main<<<M_TILES * K_SPLITS, 128>>>(x);
    fm_fin<<<64, 256>>>(gb, out);
}

// round 12
// speedup vs baseline: 1.0871x; 1.0336x over previous
#include <cuda_runtime.h>

#define BB       4096
#define VOCABN   50000
#define FF       64
#define K_PAD    50688       // 9 * 5632 = 792 * 64, B zero-padded beyond 50000
#define K_SPLITS 9
#define K_PER    5632        // 44 * 128
#define ITERS    44
#define TILE_K   128
#define M_TILES  32
#define NB       64          // V cols only; c handled via dp4a
#define BROW8    144         // int8 smem row stride (128 data + 16 pad)
#define LIMB_B   (NB * BROW8)   // 9216 bytes per limb per stage

// ---- device-global scratch (zero-initialized at load; invariant restored by fm_fin) ----
__device__ __align__(16) signed char g_Bh8[NB * K_PAD];
__device__ __align__(16) signed char g_Bl8[NB * K_PAD];
__device__ __align__(16) signed char g_ch8[K_PAD];
__device__ __align__(16) signed char g_cl8[K_PAD];
__device__ float g_xv[BB * FF];
__device__ float g_xc[BB];
__device__ int   g_maxb[2];      // [0] = max|V| (all cols), [1] = max|c|

__device__ __forceinline__ unsigned s2u(const void* p) {
    return (unsigned)__cvta_generic_to_shared(p);
}
__device__ __forceinline__ void cp16(void* dst, const void* src) {
    asm volatile("cp.async.cg.shared.global [%0], [%1], 16;"
                 :: "r"(s2u(dst)), "l"(src));
}
__device__ __forceinline__ void ldsm4(unsigned* r, unsigned addr) {
    asm volatile("ldmatrix.sync.aligned.m8n8.x4.shared.b16 {%0,%1,%2,%3}, [%4];"
                 : "=r"(r[0]), "=r"(r[1]), "=r"(r[2]), "=r"(r[3]) : "r"(addr));
}
__device__ __forceinline__ void mma_s8(int* d, const unsigned* a, unsigned b0, unsigned b1) {
    asm volatile(
        "mma.sync.aligned.m16n8k32.row.col.s32.s8.s8.s32 "
        "{%0,%1,%2,%3}, {%4,%5,%6,%7}, {%8,%9}, {%0,%1,%2,%3};"
        : "+r"(d[0]), "+r"(d[1]), "+r"(d[2]), "+r"(d[3])
        : "r"(a[0]), "r"(a[1]), "r"(a[2]), "r"(a[3]), "r"(b0), "r"(b1));
}

// ---------------- pass 1: global max|V| and max|c| (2 scalars) ----------------
__global__ void fm_scale1(const float* __restrict__ V, const float* __restrict__ bias) {
    __shared__ int sm2[2];
    int tid = threadIdx.x, lane = tid & 31;
    if (tid < 2) sm2[tid] = 0;
    __syncthreads();
    int r = blockIdx.x * 256 + tid;
    float vmax = 0.f, cabs = 0.f;
    if (r < VOCABN) {
        const float4* vr = (const float4*)(V + (size_t)r * 64);
        float ss = 0.f;
        #pragma unroll
        for (int j = 0; j < 16; j++) {
            float4 v = vr[j];
            ss += v.x*v.x + v.y*v.y + v.z*v.z + v.w*v.w;
            vmax = fmaxf(vmax, fmaxf(fmaxf(fabsf(v.x), fabsf(v.y)),
                                     fmaxf(fabsf(v.z), fabsf(v.w))));
        }
        cabs = fabsf(bias[r] - 0.5f * ss);
    }
    #pragma unroll
    for (int off = 16; off > 0; off >>= 1) {
        vmax = fmaxf(vmax, __shfl_xor_sync(0xFFFFFFFFu, vmax, off));
        cabs = fmaxf(cabs, __shfl_xor_sync(0xFFFFFFFFu, cabs, off));
    }
    if (lane == 0) {
        atomicMax(&sm2[0], __float_as_int(vmax));
        atomicMax(&sm2[1], __float_as_int(cabs));
    }
    __syncthreads();
    if (tid < 2) atomicMax(&g_maxb[tid], sm2[tid]);
}

__device__ __forceinline__ void quant2(float v, float s, signed char& h8, signed char& l8) {
    float q = v * s;
    float h = rintf(q);
    float l = rintf((q - h) * 256.f);
    if (l > 127.f) l = 127.f;
    h8 = (signed char)(int)h;
    l8 = (signed char)(int)l;
}

// ---------------- pass 2: quantize V cols + c; conflict-free transposed smem ----------------
__global__ void fm_prep(const float* __restrict__ V, const float* __restrict__ bias) {
    __shared__ float smT[64][68];     // [f][i], stride 68 -> 16B-aligned rows
    int i0 = blockIdx.x * 64;
    int tid = threadIdx.x;

    float mV = __int_as_float(g_maxb[0]);
    float sV = (mV > 0.f) ? 127.f / mV : 1.f;
    float mC = __int_as_float(g_maxb[1]);
    float sC = (mC > 0.f) ? 127.f / mC : 1.f;

    // phase 1: warp spans 32 rows at fixed f4 -> conflict-free STS
    #pragma unroll
    for (int pass = 0; pass < 4; pass++) {
        int idx = pass * 256 + tid;
        int i  = idx & 63;
        int f4 = (idx >> 6) * 4;
        int gi = i0 + i;
        float4 v = (gi < VOCABN)
                 ? *(const float4*)(V + (size_t)gi * 64 + f4)
                 : make_float4(0.f, 0.f, 0.f, 0.f);
        smT[f4 + 0][i] = v.x;
        smT[f4 + 1][i] = v.y;
        smT[f4 + 2][i] = v.z;
        smT[f4 + 3][i] = v.w;
    }
    __syncthreads();

    // c column: in-thread row sum + quant (no smem, no extra sync)
    if (tid < 64) {
        float ssum = 0.f;
        #pragma unroll
        for (int f = 0; f < 64; f++) { float v = smT[f][tid]; ssum += v * v; }
        int gi = i0 + tid;
        float cv = (gi < VOCABN) ? (bias[gi] - 0.5f * ssum) : 0.f;
        signed char h8, l8;
        quant2(cv, sC, h8, l8);
        g_ch8[i0 + tid] = h8;
        g_cl8[i0 + tid] = l8;
    }

    // phase 3: LDS.128 reads (conflict-free), char4 stores
    #pragma unroll
    for (int pass = 0; pass < 4; pass++) {
        int idx = pass * 256 + tid;
        int f  = idx >> 4;
        int i4 = (idx & 15) * 4;
        float4 v = *(const float4*)&smT[f][i4];
        char4 h4, l4;
        quant2(v.x, sV, (signed char&)h4.x, (signed char&)l4.x);
        quant2(v.y, sV, (signed char&)h4.y, (signed char&)l4.y);
        quant2(v.z, sV, (signed char&)h4.z, (signed char&)l4.z);
        quant2(v.w, sV, (signed char&)h4.w, (signed char&)l4.w);
        *(char4*)&g_Bh8[(size_t)f * K_PAD + i0 + i4] = h4;
        *(char4*)&g_Bl8[(size_t)f * K_PAD + i0 + i4] = l4;
    }
}

// ---------------- main: split-K s8 GEMM (exact s32) + dp4a linear term ----------------
__global__ void __launch_bounds__(128, 2) fm_main(const int* __restrict__ x) {
    __shared__ __align__(16) signed char sB[2][2][NB][BROW8];   // 36.9KB
    __shared__ __align__(16) signed char sC[2][2][128];          // 512B

    const int tid  = threadIdx.x;
    const int w    = tid >> 5;
    const int lane = tid & 31;
    const int gid  = lane >> 2;
    const int t4   = (lane & 3) * 4;
    const int t2   = (lane & 3) * 2;
    const int mt   = blockIdx.x & (M_TILES - 1);
    const int ks   = blockIdx.x >> 5;
    const int m0   = mt * 128;
    const int k0   = ks * K_PER;

    const int* xr[4];
    bool nl[4];
    #pragma unroll
    for (int j = 0; j < 4; j++) {
        int r = m0 + w * 32 + j * 8 + gid;
        xr[j] = x + (size_t)r * VOCABN;
        nl[j] = (r != BB - 1);
    }

    int accH[8][2][4], accL[8][2][4];
    #pragma unroll
    for (int n = 0; n < 8; n++)
        #pragma unroll
        for (int m = 0; m < 2; m++)
            #pragma unroll
            for (int i = 0; i < 4; i++) { accH[n][m][i] = 0; accL[n][m][i] = 0; }
    int cH[4] = {0, 0, 0, 0}, cL[4] = {0, 0, 0, 0};

    // stage k128: B = 2*64*8 = 1024 chunks (8/thread); c = 16 chunks
    auto stageB = [&](int st, int k) {
        #pragma unroll
        for (int j = 0; j < 8; j++) {
            int c = tid + j * 128;
            int limb = (c >= 512) ? 1 : 0;
            int cc = c - limb * 512;
            int n = cc >> 3, ch = cc & 7;
            const signed char* g = limb ? g_Bl8 : g_Bh8;
            cp16(&sB[st][limb][n][ch * 16], g + (size_t)n * K_PAD + k + ch * 16);
        }
        if (tid < 16) {
            int limb = tid >> 3, ch = tid & 7;
            const signed char* g = limb ? g_cl8 : g_ch8;
            cp16(&sC[st][limb][ch * 16], g + k + ch * 16);
        }
        asm volatile("cp.async.commit_group;");
    };

    // depth-2 A prefetch: raw[pb] loaded at step g, consumed at step g+2
    int4 raw[2][8];
    unsigned pa[8];
    auto loadA = [&](int pb, int cb) {
        #pragma unroll
        for (int mf = 0; mf < 2; mf++)
            #pragma unroll
            for (int q = 0; q < 4; q++) {
                const int* p = xr[mf * 2 + (q & 1)];
                int c = cb + (q >> 1) * 16 + t4;
                bool ok = nl[mf * 2 + (q & 1)] | (c < VOCABN);
                raw[pb][mf * 4 + q] = ok ? *(const int4*)(p + c) : make_int4(0, 0, 0, 0);
            }
    };
    auto packA = [&](int pb) {
        #pragma unroll
        for (int i = 0; i < 8; i++) {
            int4 v = raw[pb][i];
            pa[i] = (unsigned)v.x | ((unsigned)v.y << 8)
                  | ((unsigned)v.z << 16) | ((unsigned)v.w << 24);
        }
    };

    const unsigned offX4 = (unsigned)((lane & 15) * BROW8 + (lane >> 4) * 16);
    const unsigned sb0 = s2u(&sB[0][0][0][0]);

    auto doLimb = [&](unsigned lb, int (&acc)[8][2][4]) {
        #pragma unroll
        for (int j = 0; j < 4; j++) {
            unsigned bm[4];
            ldsm4(bm, lb + (unsigned)j * (16 * BROW8) + offX4);
            #pragma unroll
            for (int mf = 0; mf < 2; mf++) {
                mma_s8(acc[2 * j][mf],     pa + mf * 4, bm[0], bm[2]);
                mma_s8(acc[2 * j + 1][mf], pa + mf * 4, bm[1], bm[3]);
            }
        }
    };

    stageB(0, k0);
    loadA(0, k0);           // g = 0
    loadA(1, k0 + 32);      // g = 1

    for (int it = 0; it < ITERS; it++) {
        const int p = it & 1;
        __syncthreads();
        if (it + 1 < ITERS) {
            stageB(p ^ 1, k0 + (it + 1) * TILE_K);
            asm volatile("cp.async.wait_group 1;");
        } else {
            asm volatile("cp.async.wait_group 0;");
        }
        __syncthreads();

        // hoist the c-term weights for all 4 s-steps into registers up front
        int wc[4][4];
        #pragma unroll
        for (int s = 0; s < 4; s++) {
            wc[s][0] = *(const int*)&sC[p][0][s * 32 + t4];
            wc[s][1] = *(const int*)&sC[p][0][s * 32 + 16 + t4];
            wc[s][2] = *(const int*)&sC[p][1][s * 32 + t4];
            wc[s][3] = *(const int*)&sC[p][1][s * 32 + 16 + t4];
        }

        const unsigned stb = sb0 + (unsigned)p * (2 * LIMB_B);
        #pragma unroll
        for (int s = 0; s < 4; s++) {
            const int g = it * 4 + s;
            const int pb = g & 1;
            packA(pb);                          // consume batch loaded at g-2
            loadA(pb, k0 + (g + 2) * 32);       // issue batch for g+2
            // linear (c) term via dp4a on ALU pipe
            {
                cH[0] = __dp4a((int)pa[0], wc[s][0], cH[0]);
                cH[1] = __dp4a((int)pa[1], wc[s][0], cH[1]);
                cH[0] = __dp4a((int)pa[2], wc[s][1], cH[0]);
                cH[1] = __dp4a((int)pa[3], wc[s][1], cH[1]);
                cH[2] = __dp4a((int)pa[4], wc[s][0], cH[2]);
                cH[3] = __dp4a((int)pa[5], wc[s][0], cH[3]);
                cH[2] = __dp4a((int)pa[6], wc[s][1], cH[2]);
                cH[3] = __dp4a((int)pa[7], wc[s][1], cH[3]);
                cL[0] = __dp4a((int)pa[0], wc[s][2], cL[0]);
                cL[1] = __dp4a((int)pa[1], wc[s][2], cL[1]);
                cL[0] = __dp4a((int)pa[2], wc[s][3], cL[0]);
                cL[1] = __dp4a((int)pa[3], wc[s][3], cL[1]);
                cL[2] = __dp4a((int)pa[4], wc[s][2], cL[2]);
                cL[3] = __dp4a((int)pa[5], wc[s][2], cL[3]);
                cL[2] = __dp4a((int)pa[6], wc[s][3], cL[2]);
                cL[3] = __dp4a((int)pa[7], wc[s][3], cL[3]);
            }
            doLimb(stb + (unsigned)s * 32, accH);
            doLimb(stb + LIMB_B + (unsigned)s * 32, accL);
        }
    }

    // ---- epilogue: dequant + split-K accumulate ----
    float mV = __int_as_float(g_maxb[0]);
    float mC = __int_as_float(g_maxb[1]);
    const double invV = (mV > 0.f) ? (double)mV / 32512.0 : (1.0 / 256.0);
    const double invC = (mC > 0.f) ? (double)mC / 32512.0 : (1.0 / 256.0);

    #pragma unroll
    for (int mf = 0; mf < 2; mf++) {
        int rowA = m0 + w * 32 + mf * 16 + gid;
        #pragma unroll
        for (int nf = 0; nf < 8; nf++) {
            #pragma unroll
            for (int cc = 0; cc < 2; cc++) {
                int n = nf * 8 + t2 + cc;
                float v0 = (float)((double)(256LL * accH[nf][mf][cc]     + accL[nf][mf][cc])     * invV);
                float v1 = (float)((double)(256LL * accH[nf][mf][2 + cc] + accL[nf][mf][2 + cc]) * invV);
                atomicAdd(&g_xv[(size_t)rowA * FF + n],       v0);
                atomicAdd(&g_xv[(size_t)(rowA + 8) * FF + n], v1);
            }
        }
    }
    // c term: quad-reduce then one atomic per row slot
    #pragma unroll
    for (int j = 0; j < 4; j++) {
        int h = cH[j], l = cL[j];
        h += __shfl_xor_sync(0xFFFFFFFFu, h, 1);
        h += __shfl_xor_sync(0xFFFFFFFFu, h, 2);
        l += __shfl_xor_sync(0xFFFFFFFFu, l, 1);
        l += __shfl_xor_sync(0xFFFFFFFFu, l, 2);
        if ((lane & 3) == 0) {
            int row = m0 + w * 32 + j * 8 + gid;
            atomicAdd(&g_xc[row],
                      (float)((double)(256LL * h + l) * invC));
        }
    }
}

// ---------------- finalize: out = g + xc + 0.5||xv||^2; re-zero scratch ----------------
__global__ void fm_fin(const float* __restrict__ gb, float* __restrict__ out) {
    int t = blockIdx.x * blockDim.x + threadIdx.x;   // 16384 threads
    int b = t >> 2, part = t & 3;
    float4* v = (float4*)&g_xv[(size_t)b * FF + part * 16];
    float ss = 0.f;
    #pragma unroll
    for (int i = 0; i < 4; i++) {
        float4 q = v[i];
        ss += q.x * q.x + q.y * q.y + q.z * q.z + q.w * q.w;
        v[i] = make_float4(0.f, 0.f, 0.f, 0.f);          // restore zero invariant
    }
    ss += __shfl_xor_sync(0xFFFFFFFFu, ss, 1);
    ss += __shfl_xor_sync(0xFFFFFFFFu, ss, 2);
    if (part == 0) {
        out[b] = gb[0] + g_xc[b] + 0.5f * ss;
        g_xc[b] = 0.f;
    }
    if (t < 2) g_maxb[t] = 0;
}

extern "C" void kernel_launch(void* const* d_in, const int* in_sizes, int n_in,
                              void* d_out, int out_size) {
    const int*   x    = (const int*)d_in[0];
    const float* V    = (const float*)d_in[1];
    const float* bias = (const float*)d_in[2];
    const float* gb   = (const float*)d_in[3];
    float* out = (float*)d_out;
    (void)in_sizes; (void)n_in; (void)out_size;

    fm_scale1<<<196, 256>>>(V, bias);
    fm_prep<<<K_PAD / 64, 256>>>(V, bias);
    fm_main<<<M_TILES * K_SPLITS, 128>>>(x);
    fm_fin<<<64, 256>>>(gb, out);
}

// round 13
// speedup vs baseline: 1.1907x; 1.0952x over previous
#include <cuda_runtime.h>

#define BB       4096
#define VOCABN   50000
#define FF       64
#define K_PAD    50688       // 9 * 5632 = 792 * 64, B zero-padded beyond 50000
#define K_SPLITS 9
#define K_PER    5632        // 44 * 128
#define ITERS    44
#define TILE_K   128
#define M_TILES  32
#define NB       64          // V cols only; c handled via dp4a
#define BROW8    144         // int8 smem row stride (128 data + 16 pad)
#define LIMB_B   (NB * BROW8)   // 9216 bytes per limb per stage
#define SC_OFF   36864          // sC after sB (2*2*LIMB_B = 36864)
#define A_OFF    37376          // A ring after sC (512B, 16B aligned)
#define A_SLOT   16384          // 128 threads * 8 chunks * 16B
#define SMEM_MAIN (A_OFF + 4 * A_SLOT)   // 102912 bytes

// ---- device-global scratch (zero-initialized at load; invariant restored by fm_fin) ----
__device__ __align__(16) signed char g_Bh8[NB * K_PAD];
__device__ __align__(16) signed char g_Bl8[NB * K_PAD];
__device__ __align__(16) signed char g_ch8[K_PAD];
__device__ __align__(16) signed char g_cl8[K_PAD];
__device__ float g_xv[BB * FF];
__device__ float g_xc[BB];
__device__ int   g_maxb[2];      // [0] = max|V|, [1] = max|c|

__device__ __forceinline__ unsigned s2u(const void* p) {
    return (unsigned)__cvta_generic_to_shared(p);
}
__device__ __forceinline__ void cp16(void* dst, const void* src) {
    asm volatile("cp.async.cg.shared.global [%0], [%1], 16;"
                 :: "r"(s2u(dst)), "l"(src));
}
__device__ __forceinline__ void ldsm4(unsigned* r, unsigned addr) {
    asm volatile("ldmatrix.sync.aligned.m8n8.x4.shared.b16 {%0,%1,%2,%3}, [%4];"
                 : "=r"(r[0]), "=r"(r[1]), "=r"(r[2]), "=r"(r[3]) : "r"(addr));
}
__device__ __forceinline__ void mma_s8(int* d, const unsigned* a, unsigned b0, unsigned b1) {
    asm volatile(
        "mma.sync.aligned.m16n8k32.row.col.s32.s8.s8.s32 "
        "{%0,%1,%2,%3}, {%4,%5,%6,%7}, {%8,%9}, {%0,%1,%2,%3};"
        : "+r"(d[0]), "+r"(d[1]), "+r"(d[2]), "+r"(d[3])
        : "r"(a[0]), "r"(a[1]), "r"(a[2]), "r"(a[3]), "r"(b0), "r"(b1));
}

// ---------------- pass 1: global max|V| and max|c| ----------------
__global__ void fm_scale1(const float* __restrict__ V, const float* __restrict__ bias) {
    __shared__ int sm2[2];
    int tid = threadIdx.x, lane = tid & 31;
    if (tid < 2) sm2[tid] = 0;
    __syncthreads();
    int r = blockIdx.x * 256 + tid;
    float vmax = 0.f, cabs = 0.f;
    if (r < VOCABN) {
        const float4* vr = (const float4*)(V + (size_t)r * 64);
        float ss = 0.f;
        #pragma unroll
        for (int j = 0; j < 16; j++) {
            float4 v = vr[j];
            ss += v.x*v.x + v.y*v.y + v.z*v.z + v.w*v.w;
            vmax = fmaxf(vmax, fmaxf(fmaxf(fabsf(v.x), fabsf(v.y)),
                                     fmaxf(fabsf(v.z), fabsf(v.w))));
        }
        cabs = fabsf(bias[r] - 0.5f * ss);
    }
    #pragma unroll
    for (int off = 16; off > 0; off >>= 1) {
        vmax = fmaxf(vmax, __shfl_xor_sync(0xFFFFFFFFu, vmax, off));
        cabs = fmaxf(cabs, __shfl_xor_sync(0xFFFFFFFFu, cabs, off));
    }
    if (lane == 0) {
        atomicMax(&sm2[0], __float_as_int(vmax));
        atomicMax(&sm2[1], __float_as_int(cabs));
    }
    __syncthreads();
    if (tid < 2) atomicMax(&g_maxb[tid], sm2[tid]);
}

__device__ __forceinline__ void quant2(float v, float s, signed char& h8, signed char& l8) {
    float q = v * s;
    float h = rintf(q);
    float l = rintf((q - h) * 256.f);
    if (l > 127.f) l = 127.f;
    h8 = (signed char)(int)h;
    l8 = (signed char)(int)l;
}

// ---------------- pass 2: quantize V cols + c; conflict-free transposed smem ----------------
__global__ void fm_prep(const float* __restrict__ V, const float* __restrict__ bias) {
    __shared__ float smT[64][68];
    int i0 = blockIdx.x * 64;
    int tid = threadIdx.x;

    float mV = __int_as_float(g_maxb[0]);
    float sV = (mV > 0.f) ? 127.f / mV : 1.f;
    float mC = __int_as_float(g_maxb[1]);
    float sC = (mC > 0.f) ? 127.f / mC : 1.f;

    #pragma unroll
    for (int pass = 0; pass < 4; pass++) {
        int idx = pass * 256 + tid;
        int i  = idx & 63;
        int f4 = (idx >> 6) * 4;
        int gi = i0 + i;
        float4 v = (gi < VOCABN)
                 ? *(const float4*)(V + (size_t)gi * 64 + f4)
                 : make_float4(0.f, 0.f, 0.f, 0.f);
        smT[f4 + 0][i] = v.x;
        smT[f4 + 1][i] = v.y;
        smT[f4 + 2][i] = v.z;
        smT[f4 + 3][i] = v.w;
    }
    __syncthreads();

    if (tid < 64) {
        float ssum = 0.f;
        #pragma unroll
        for (int f = 0; f < 64; f++) { float v = smT[f][tid]; ssum += v * v; }
        int gi = i0 + tid;
        float cv = (gi < VOCABN) ? (bias[gi] - 0.5f * ssum) : 0.f;
        signed char h8, l8;
        quant2(cv, sC, h8, l8);
        g_ch8[i0 + tid] = h8;
        g_cl8[i0 + tid] = l8;
    }

    #pragma unroll
    for (int pass = 0; pass < 4; pass++) {
        int idx = pass * 256 + tid;
        int f  = idx >> 4;
        int i4 = (idx & 15) * 4;
        float4 v = *(const float4*)&smT[f][i4];
        char4 h4, l4;
        quant2(v.x, sV, (signed char&)h4.x, (signed char&)l4.x);
        quant2(v.y, sV, (signed char&)h4.y, (signed char&)l4.y);
        quant2(v.z, sV, (signed char&)h4.z, (signed char&)l4.z);
        quant2(v.w, sV, (signed char&)h4.w, (signed char&)l4.w);
        *(char4*)&g_Bh8[(size_t)f * K_PAD + i0 + i4] = h4;
        *(char4*)&g_Bl8[(size_t)f * K_PAD + i0 + i4] = l4;
    }
}

// ---------------- main: split-K s8 GEMM + dp4a linear term; cp.async A ring ----------------
__global__ void __launch_bounds__(128, 2) fm_main(const int* __restrict__ x) {
    extern __shared__ __align__(16) char dsm[];
    const unsigned sbase = s2u(dsm);

    const int tid  = threadIdx.x;
    const int w    = tid >> 5;
    const int lane = tid & 31;
    const int gid  = lane >> 2;
    const int t4   = (lane & 3) * 4;
    const int t2   = (lane & 3) * 2;
    const int mt   = blockIdx.x & (M_TILES - 1);
    const int ks   = blockIdx.x >> 5;
    const int m0   = mt * 128;
    const int k0   = ks * K_PER;

    const int* xr[4];
    bool nl[4];
    #pragma unroll
    for (int j = 0; j < 4; j++) {
        int r = m0 + w * 32 + j * 8 + gid;
        xr[j] = x + (size_t)r * VOCABN;
        nl[j] = (r != BB - 1);
    }

    int accH[8][2][4], accL[8][2][4];
    #pragma unroll
    for (int n = 0; n < 8; n++)
        #pragma unroll
        for (int m = 0; m < 2; m++)
            #pragma unroll
            for (int i = 0; i < 4; i++) { accH[n][m][i] = 0; accL[n][m][i] = 0; }
    int cH[4] = {0, 0, 0, 0}, cL[4] = {0, 0, 0, 0};

    // stage k128 of B (both limbs) + c chunk; one commit
    auto stageB = [&](int st, int k) {
        #pragma unroll
        for (int j = 0; j < 8; j++) {
            int c = tid + j * 128;
            int limb = (c >= 512) ? 1 : 0;
            int cc = c - limb * 512;
            int n = cc >> 3, ch = cc & 7;
            const signed char* g = limb ? g_Bl8 : g_Bh8;
            cp16(dsm + st * (2 * LIMB_B) + limb * LIMB_B + n * BROW8 + ch * 16,
                 g + (size_t)n * K_PAD + k + ch * 16);
        }
        if (tid < 16) {
            int limb = tid >> 3, ch = tid & 7;
            const signed char* g = limb ? g_cl8 : g_ch8;
            cp16(dsm + SC_OFF + st * 256 + limb * 128 + ch * 16, g + k + ch * 16);
        }
        asm volatile("cp.async.commit_group;");
    };

    // stage A batch g into ring slot g&3 (8x16B per thread, self-consumed); one commit
    auto cpA = [&](int g) {
        char* base = dsm + A_OFF + (g & 3) * A_SLOT + tid * 16;
        int cb = k0 + g * 32;
        #pragma unroll
        for (int mf = 0; mf < 2; mf++)
            #pragma unroll
            for (int q = 0; q < 4; q++) {
                int i = mf * 4 + q;
                const int* p = xr[mf * 2 + (q & 1)];
                int c = cb + (q >> 1) * 16 + t4;
                char* dst = base + i * 2048;
                if (nl[mf * 2 + (q & 1)] | (c < VOCABN)) cp16(dst, p + c);
                else *(int4*)dst = make_int4(0, 0, 0, 0);
            }
        asm volatile("cp.async.commit_group;");
    };

    unsigned pa[8];
    auto consumeA = [&](int g) {
        const char* base = dsm + A_OFF + (g & 3) * A_SLOT + tid * 16;
        #pragma unroll
        for (int i = 0; i < 8; i++) {
            int4 v = *(const int4*)(base + i * 2048);
            pa[i] = (unsigned)v.x | ((unsigned)v.y << 8)
                  | ((unsigned)v.z << 16) | ((unsigned)v.w << 24);
        }
    };

    const unsigned offX4 = (unsigned)((lane & 15) * BROW8 + (lane >> 4) * 16);

    auto doLimb = [&](unsigned lb, int (&acc)[8][2][4]) {
        #pragma unroll
        for (int j = 0; j < 4; j++) {
            unsigned bm[4];
            ldsm4(bm, lb + (unsigned)j * (16 * BROW8) + offX4);
            #pragma unroll
            for (int mf = 0; mf < 2; mf++) {
                mma_s8(acc[2 * j][mf],     pa + mf * 4, bm[0], bm[2]);
                mma_s8(acc[2 * j + 1][mf], pa + mf * 4, bm[1], bm[3]);
            }
        }
    };

    // prologue: B stage 0 + A batches 0..2; ensure B(0) arrived (A0..A2 may stay pending)
    stageB(0, k0);
    cpA(0); cpA(1); cpA(2);
    asm volatile("cp.async.wait_group 3;");

    for (int it = 0; it < ITERS; it++) {
        const int p = it & 1;
        __syncthreads();   // orders prior-iter waits (visibility) + protects stage reuse
        if (it + 1 < ITERS) stageB(p ^ 1, k0 + (it + 1) * TILE_K);

        // c-term weights for all 4 s-steps (stage p data: arrived + visible)
        int wc[4][4];
        #pragma unroll
        for (int s = 0; s < 4; s++) {
            wc[s][0] = *(const int*)(dsm + SC_OFF + p * 256 + s * 32 + t4);
            wc[s][1] = *(const int*)(dsm + SC_OFF + p * 256 + s * 32 + 16 + t4);
            wc[s][2] = *(const int*)(dsm + SC_OFF + p * 256 + 128 + s * 32 + t4);
            wc[s][3] = *(const int*)(dsm + SC_OFF + p * 256 + 128 + s * 32 + 16 + t4);
        }

        const unsigned stb = sbase + (unsigned)p * (2 * LIMB_B);
        #pragma unroll
        for (int s = 0; s < 4; s++) {
            const int g = it * 4 + s;
            // allows the 2 most recent groups pending -> A(g) and B(stage p) complete
            asm volatile("cp.async.wait_group 2;");
            cpA(g + 3);                         // refill slot consumed at step g-1
            consumeA(g);
            {
                cH[0] = __dp4a((int)pa[0], wc[s][0], cH[0]);
                cH[1] = __dp4a((int)pa[1], wc[s][0], cH[1]);
                cH[0] = __dp4a((int)pa[2], wc[s][1], cH[0]);
                cH[1] = __dp4a((int)pa[3], wc[s][1], cH[1]);
                cH[2] = __dp4a((int)pa[4], wc[s][0], cH[2]);
                cH[3] = __dp4a((int)pa[5], wc[s][0], cH[3]);
                cH[2] = __dp4a((int)pa[6], wc[s][1], cH[2]);
                cH[3] = __dp4a((int)pa[7], wc[s][1], cH[3]);
                cL[0] = __dp4a((int)pa[0], wc[s][2], cL[0]);
                cL[1] = __dp4a((int)pa[1], wc[s][2], cL[1]);
                cL[0] = __dp4a((int)pa[2], wc[s][3], cL[0]);
                cL[1] = __dp4a((int)pa[3], wc[s][3], cL[1]);
                cL[2] = __dp4a((int)pa[4], wc[s][2], cL[2]);
                cL[3] = __dp4a((int)pa[5], wc[s][2], cL[3]);
                cL[2] = __dp4a((int)pa[6], wc[s][3], cL[2]);
                cL[3] = __dp4a((int)pa[7], wc[s][3], cL[3]);
            }
            doLimb(stb + (unsigned)s * 32, accH);
            doLimb(stb + LIMB_B + (unsigned)s * 32, accL);
        }
    }

    // ---- epilogue: dequant + split-K accumulate ----
    float mV = __int_as_float(g_maxb[0]);
    float mC = __int_as_float(g_maxb[1]);
    const double invV = (mV > 0.f) ? (double)mV / 32512.0 : (1.0 / 256.0);
    const double invC = (mC > 0.f) ? (double)mC / 32512.0 : (1.0 / 256.0);

    #pragma unroll
    for (int mf = 0; mf < 2; mf++) {
        int rowA = m0 + w * 32 + mf * 16 + gid;
        #pragma unroll
        for (int nf = 0; nf < 8; nf++) {
            #pragma unroll
            for (int cc = 0; cc < 2; cc++) {
                int n = nf * 8 + t2 + cc;
                float v0 = (float)((double)(256LL * accH[nf][mf][cc]     + accL[nf][mf][cc])     * invV);
                float v1 = (float)((double)(256LL * accH[nf][mf][2 + cc] + accL[nf][mf][2 + cc]) * invV);
                atomicAdd(&g_xv[(size_t)rowA * FF + n],       v0);
                atomicAdd(&g_xv[(size_t)(rowA + 8) * FF + n], v1);
            }
        }
    }
    #pragma unroll
    for (int j = 0; j < 4; j++) {
        int h = cH[j], l = cL[j];
        h += __shfl_xor_sync(0xFFFFFFFFu, h, 1);
        h += __shfl_xor_sync(0xFFFFFFFFu, h, 2);
        l += __shfl_xor_sync(0xFFFFFFFFu, l, 1);
        l += __shfl_xor_sync(0xFFFFFFFFu, l, 2);
        if ((lane & 3) == 0) {
            int row = m0 + w * 32 + j * 8 + gid;
            atomicAdd(&g_xc[row],
                      (float)((double)(256LL * h + l) * invC));
        }
    }
}

// ---------------- finalize: out = g + xc + 0.5||xv||^2; re-zero scratch ----------------
__global__ void fm_fin(const float* __restrict__ gb, float* __restrict__ out) {
    int t = blockIdx.x * blockDim.x + threadIdx.x;
    int b = t >> 2, part = t & 3;
    float4* v = (float4*)&g_xv[(size_t)b * FF + part * 16];
    float ss = 0.f;
    #pragma unroll
    for (int i = 0; i < 4; i++) {
        float4 q = v[i];
        ss += q.x * q.x + q.y * q.y + q.z * q.z + q.w * q.w;
        v[i] = make_float4(0.f, 0.f, 0.f, 0.f);
    }
    ss += __shfl_xor_sync(0xFFFFFFFFu, ss, 1);
    ss += __shfl_xor_sync(0xFFFFFFFFu, ss, 2);
    if (part == 0) {
        out[b] = gb[0] + g_xc[b] + 0.5f * ss;
        g_xc[b] = 0.f;
    }
    if (t < 2) g_maxb[t] = 0;
}

extern "C" void kernel_launch(void* const* d_in, const int* in_sizes, int n_in,
                              void* d_out, int out_size) {
    const int*   x    = (const int*)d_in[0];
    const float* V    = (const float*)d_in[1];
    const float* bias = (const float*)d_in[2];
    const float* gb   = (const float*)d_in[3];
    float* out = (float*)d_out;
    (void)in_sizes; (void)n_in; (void)out_size;

    cudaFuncSetAttribute(fm_main, cudaFuncAttributeMaxDynamicSharedMemorySize, SMEM_MAIN);

    fm_scale1<<<196, 256>>>(V, bias);
    fm_prep<<<K_PAD / 64, 256>>>(V, bias);
    fm_main<<<M_TILES * K_SPLITS, 128, SMEM_MAIN>>>(x);
    fm_fin<<<64, 256>>>(gb, out);
}